// round 14
// baseline (speedup 1.0000x reference)
#include <cuda_runtime.h>
#include <cuda_bf16.h>

// ---------------------------------------------------------------------------
// GATv2 x2, heads=1, edge_dim=1, self-loops fill='mean'.
// N=100000, E=1600000, IN=128, HID=OUT=32.
// R13: GEMM warps specialized per matrix (0-3: Wl/xl, 4-7: Wr/xr); each
//      lane's W column cached in REGISTERS once per kernel -> steady-state
//      smem traffic is x broadcasts only. Persistent blocks + cp.async ring
//      kept. Edge pass unchanged (264us design).
// ---------------------------------------------------------------------------

#define NN 100000
#define EE 1600000
#define F 32

using u64 = unsigned long long;

__device__ float g_xl[NN * F];
__device__ float g_xr[NN * F];
__device__ float g_agg[NN * F];
__device__ float g_h[NN * F];
__device__ float g_z[NN];
__device__ float g_cnt[NN];
__device__ float g_asum[NN];
__device__ float g_mean[NN];

__device__ __forceinline__ float lrelu(float v) {
    return v > 0.0f ? v : 0.2f * v;
}

// packed dual-fp32 fma: d = a*b + c  (elementwise on {lo,hi})
__device__ __forceinline__ void fma2(u64& d, u64 a, u64 b, u64 c) {
    asm("fma.rn.f32x2 %0, %1, %2, %3;" : "=l"(d) : "l"(a), "l"(b), "l"(c));
}
__device__ __forceinline__ float fold2(u64 v) {
    float lo, hi;
    asm("mov.b64 {%0, %1}, %2;" : "=f"(lo), "=f"(hi) : "l"(v));
    return lo + hi;
}

__device__ __forceinline__ unsigned smem_u32(const void* p) {
    unsigned a;
    asm("{ .reg .u64 t; cvta.to.shared.u64 t, %1; cvt.u32.u64 %0, t; }"
        : "=r"(a) : "l"(p));
    return a;
}
__device__ __forceinline__ void cp16(unsigned dst, const void* src) {
    asm volatile("cp.async.cg.shared.global [%0], [%1], 16;"
                 :: "r"(dst), "l"(src) : "memory");
}
__device__ __forceinline__ void cp_commit() {
    asm volatile("cp.async.commit_group;" ::: "memory");
}
template <int N_>
__device__ __forceinline__ void cp_wait() {
    asm volatile("cp.async.wait_group %0;" :: "n"(N_) : "memory");
}

// --------------------------- small / init kernels ---------------------------

__global__ void k_zero2(float* a, float* b, int n) {
    for (int i = blockIdx.x * blockDim.x + threadIdx.x; i < n;
         i += gridDim.x * blockDim.x) { a[i] = 0.0f; b[i] = 0.0f; }
}

__global__ void k_init(float* z, float* agg, int n) {
    int tid = blockIdx.x * blockDim.x + threadIdx.x;
    int stride = gridDim.x * blockDim.x;
    for (int i = tid; i < n; i += stride) z[i] = 0.0f;
    for (int i = tid; i < n * F; i += stride) agg[i] = 0.0f;
}

__global__ void k_deg(const int* __restrict__ dst, const float* __restrict__ ea, int e) {
    int i = blockIdx.x * blockDim.x + threadIdx.x;
    if (i >= e) return;
    int d = dst[i];
    atomicAdd(&g_cnt[d], 1.0f);
    atomicAdd(&g_asum[d], ea[i]);
}

__global__ void k_mean(int n) {
    int i = blockIdx.x * blockDim.x + threadIdx.x;
    if (i >= n) return;
    g_mean[i] = g_asum[i] / fmaxf(g_cnt[i], 1.0f);
}

// ------------------------------- dense GEMM --------------------------------
// Persistent blocks, cp.async double-buffered x stream. 8 warps:
//   warps 0-3 compute xl (Wl), warps 4-7 compute xr (Wr); warp handles 8
//   nodes of the 32-node tile; lane = output column. Each lane caches its
//   W column (k-pair packed u64) in registers ONCE -> no W smem reads in
//   the steady-state loop; x reads are lane-uniform broadcasts.
// NOTE: n must be a multiple of 32 (100000 = 3125*32 — holds here).
template <int K>
__global__ void __launch_bounds__(256, 1)
k_gemm_lr(const float* __restrict__ x,
          const float* __restrict__ Wl, const float* __restrict__ bl,
          const float* __restrict__ Wr, const float* __restrict__ br,
          float* __restrict__ xl, float* __restrict__ xr, int n) {
    constexpr int KP = K + 4;
    constexpr int TILE_FLOATS = 32 * K;           // floats per node tile
    constexpr int CP_PER_THREAD = TILE_FLOATS / (256 * 4);  // 16B ops per thread
    extern __shared__ float sm[];
    float* sWl = sm;                       // F * KP
    float* sWr = sm + F * KP;              // F * KP
    float* sx0 = sm + 2 * F * KP;          // TILE_FLOATS
    float* sx1 = sx0 + TILE_FLOATS;        // TILE_FLOATS

    const int ntiles = n >> 5;
    unsigned sx_u32[2] = { smem_u32(sx0), smem_u32(sx1) };

    // Prologue: issue first tile into buffer 0 (overlaps weight staging)
    int tile = blockIdx.x;
    if (tile < ntiles) {
        const char* srcb = (const char*)(x + (size_t)tile * TILE_FLOATS);
#pragma unroll
        for (int j = 0; j < CP_PER_THREAD; j++) {
            int off = (threadIdx.x + j * 256) * 16;
            cp16(sx_u32[0] + off, srcb + off);
        }
    }
    cp_commit();

    // Stage weights transposed+padded in smem (once), then lift to registers.
    for (int i = threadIdx.x; i < K * F; i += 256) {
        int k = i / F, c = i % F;
        sWl[c * KP + k] = Wl[i];
        sWr[c * KP + k] = Wr[i];
    }
    __syncthreads();

    int lane = threadIdx.x & 31;
    int w    = threadIdx.x >> 5;
    const float* sWT = (w < 4) ? sWl : sWr;
    u64 wreg[K / 2];
#pragma unroll
    for (int i = 0; i < K / 2; i++)
        wreg[i] = *(const u64*)&sWT[lane * KP + 2 * i];

    float bias = (w < 4) ? bl[lane] : br[lane];
    float* outp = (w < 4) ? xl : xr;
    const int nodeoff = (w & 3) * 8;
    int buf = 0;

    for (; tile < ntiles; tile += gridDim.x) {
        // Prefetch next tile into the other buffer
        int nxt = tile + gridDim.x;
        if (nxt < ntiles) {
            const char* srcb = (const char*)(x + (size_t)nxt * TILE_FLOATS);
#pragma unroll
            for (int j = 0; j < CP_PER_THREAD; j++) {
                int off = (threadIdx.x + j * 256) * 16;
                cp16(sx_u32[buf ^ 1] + off, srcb + off);
            }
        }
        cp_commit();
        cp_wait<1>();          // current tile's group has landed
        __syncthreads();

        const float* sx = buf ? sx1 : sx0;
        u64 acc[8] = {0ull, 0ull, 0ull, 0ull, 0ull, 0ull, 0ull, 0ull};
#pragma unroll
        for (int kk = 0; kk < K; kk += 4) {
#pragma unroll
            for (int j = 0; j < 8; j++) {
                // lane-uniform 16B broadcast: x[node][kk..kk+3]
                ulonglong2 xv = *(const ulonglong2*)&sx[(nodeoff + j) * K + kk];
                fma2(acc[j], xv.x, wreg[kk / 2],     acc[j]);
                fma2(acc[j], xv.y, wreg[kk / 2 + 1], acc[j]);
            }
        }
        int base = tile * 32;
#pragma unroll
        for (int j = 0; j < 8; j++)
            outp[(base + nodeoff + j) * F + lane] = fold2(acc[j]) + bias;
        __syncthreads();       // all reads of sx[buf] done before reuse
        buf ^= 1;
    }
}

// ---------------------------- fused edge pass ------------------------------
// 8 lanes per edge. Coalesced float4 gathers of xl[src]/xr[dst], butterfly
// score reduction over the 8-lane group, p = exp(s) (no max shift needed),
// z[dst] += p (lane 0), agg[dst] += p*xl[src] via red.global.add.v4.f32.
__global__ void k_edge(const int* __restrict__ src, const int* __restrict__ dst,
                       const float* __restrict__ ea,
                       const float* __restrict__ We, const float* __restrict__ att,
                       float* __restrict__ agg, float* __restrict__ z,
                       int e_real, int etot) {
    int t = blockIdx.x * blockDim.x + threadIdx.x;
    int e = t >> 3;
    if (e >= etot) return;
    int sub = t & 7;

    int s_i, d_i; float a;
    if (e < e_real) { s_i = src[e]; d_i = dst[e]; a = ea[e]; }
    else            { s_i = d_i = e - e_real;     a = g_mean[e - e_real]; }

    float4 u = *(const float4*)(g_xl + s_i * F + sub * 4);
    float4 v = *(const float4*)(g_xr + d_i * F + sub * 4);
    float4 w = __ldg((const float4*)We + sub);
    float4 tt = __ldg((const float4*)att + sub);

    float acc;
    acc = lrelu(u.x + v.x + a * w.x) * tt.x;
    acc = fmaf(lrelu(u.y + v.y + a * w.y), tt.y, acc);
    acc = fmaf(lrelu(u.z + v.z + a * w.z), tt.z, acc);
    acc = fmaf(lrelu(u.w + v.w + a * w.w), tt.w, acc);

    acc += __shfl_xor_sync(0xffffffffu, acc, 4);
    acc += __shfl_xor_sync(0xffffffffu, acc, 2);
    acc += __shfl_xor_sync(0xffffffffu, acc, 1);

    float p = __expf(acc);
    if (sub == 0) atomicAdd(&z[d_i], p);

    float px = p * u.x, py = p * u.y, pz = p * u.z, pw = p * u.w;
    float* o = agg + d_i * F + sub * 4;
    asm volatile("red.global.add.v4.f32 [%0], {%1,%2,%3,%4};"
                 :: "l"(o), "f"(px), "f"(py), "f"(pz), "f"(pw) : "memory");
}

// ------------------------------- epilogues ---------------------------------

__global__ void k_epi_relu(const float* __restrict__ agg, const float* __restrict__ z,
                           const float* __restrict__ b, float* __restrict__ h, int n) {
    int i = blockIdx.x * blockDim.x + threadIdx.x;
    if (i >= n * F) return;
    h[i] = fmaxf(agg[i] / z[i >> 5] + b[i & (F - 1)], 0.0f);
}

__global__ void k_epi(float* __restrict__ out, const float* __restrict__ z,
                      const float* __restrict__ b, int n) {
    int i = blockIdx.x * blockDim.x + threadIdx.x;
    if (i >= n * F) return;
    out[i] = out[i] / z[i >> 5] + b[i & (F - 1)];
}

// ---------------------------------------------------------------------------

extern "C" void kernel_launch(void* const* d_in, const int* in_sizes, int n_in,
                              void* d_out, int out_size) {
    const float* x   = (const float*)d_in[0];
    const int*   src = (const int*)d_in[1];
    const int*   dst = (const int*)d_in[2];
    const float* ea  = (const float*)d_in[3];
    const float* Wl1 = (const float*)d_in[4];
    const float* bl1 = (const float*)d_in[5];
    const float* Wr1 = (const float*)d_in[6];
    const float* br1 = (const float*)d_in[7];
    const float* We1 = (const float*)d_in[8];
    const float* at1 = (const float*)d_in[9];
    const float* b1  = (const float*)d_in[10];
    const float* Wl2 = (const float*)d_in[11];
    const float* bl2 = (const float*)d_in[12];
    const float* Wr2 = (const float*)d_in[13];
    const float* br2 = (const float*)d_in[14];
    const float* We2 = (const float*)d_in[15];
    const float* at2 = (const float*)d_in[16];
    const float* b2  = (const float*)d_in[17];

    const int n    = in_sizes[0] / 128;   // 100000
    const int e    = in_sizes[1];         // 1600000
    const int etot = e + n;

    float* out = (float*)d_out;
    float* d_xl;   cudaGetSymbolAddress((void**)&d_xl,   g_xl);
    float* d_xr;   cudaGetSymbolAddress((void**)&d_xr,   g_xr);
    float* d_agg;  cudaGetSymbolAddress((void**)&d_agg,  g_agg);
    float* d_h;    cudaGetSymbolAddress((void**)&d_h,    g_h);
    float* d_z;    cudaGetSymbolAddress((void**)&d_z,    g_z);
    float* d_cnt;  cudaGetSymbolAddress((void**)&d_cnt,  g_cnt);
    float* d_asum; cudaGetSymbolAddress((void**)&d_asum, g_asum);

    const int T = 256;
    const int gN   = (n + T - 1) / T;
    const int gNF  = (n * F + T - 1) / T;
    const int gE   = (e + T - 1) / T;
    const int gEW  = (etot * 8 + T - 1) / T;   // 8 lanes per edge
    const int gP   = 148;                      // persistent GEMM grid (1/SM)

    const int smem128 = (2 * F * (128 + 4) + 2 * 32 * 128) * sizeof(float); // ~66.5KB
    const int smem32  = (2 * F * (32 + 4)  + 2 * 32 * 32)  * sizeof(float); // ~17.4KB
    cudaFuncSetAttribute(k_gemm_lr<128>, cudaFuncAttributeMaxDynamicSharedMemorySize, smem128);

    // Self-loop mean edge_attr (shared by both layers)
    k_zero2<<<gN, T>>>(d_cnt, d_asum, n);
    k_deg<<<gE, T>>>(dst, ea, e);
    k_mean<<<gN, T>>>(n);

    // ---------------- Layer 1 ----------------
    k_gemm_lr<128><<<gP, T, smem128>>>(x, Wl1, bl1, Wr1, br1, d_xl, d_xr, n);
    k_init<<<gNF, T>>>(d_z, d_agg, n);
    k_edge<<<gEW, T>>>(src, dst, ea, We1, at1, d_agg, d_z, e, etot);
    k_epi_relu<<<gNF, T>>>(d_agg, d_z, b1, d_h, n);

    // ---------------- Layer 2 ----------------
    k_gemm_lr<32><<<gP, T, smem32>>>(d_h, Wl2, bl2, Wr2, br2, d_xl, d_xr, n);
    k_init<<<gNF, T>>>(d_z, out, n);
    k_edge<<<gEW, T>>>(src, dst, ea, We2, at2, out, d_z, e, etot);
    k_epi<<<gNF, T>>>(out, d_z, b2, n);
}

// round 16
// speedup vs baseline: 1.0216x; 1.0216x over previous
#include <cuda_runtime.h>
#include <cuda_bf16.h>

// ---------------------------------------------------------------------------
// GATv2 x2, heads=1, edge_dim=1, self-loops fill='mean'.
// N=100000, E=1600000, IN=128, HID=OUT=32.
// R14 (resubmit): CSR-grouped edge processing. Build CSR by dst once per
//      launch (histogram -> 3-kernel scan -> scatter), then ONE fused
//      warp-per-node kernel per layer: score + softmax + aggregate +
//      bias(+relu) entirely in registers. Kills k_init/k_epi/agg-atomics/
//      z-atomics and the per-edge xr re-gather. GEMM unchanged from R13.
// ---------------------------------------------------------------------------

#define NN 100000
#define EE 1600000
#define F 32

using u64 = unsigned long long;

__device__ float  g_xl[NN * F];
__device__ float  g_xr[NN * F];
__device__ float  g_h[NN * F];
__device__ int    g_cnt[NN];
__device__ int    g_fill[NN];
__device__ float  g_asum[NN];
__device__ float  g_mean[NN];
__device__ int    g_rowptr[NN + 1];
__device__ int    g_bsum[512];
__device__ float2 g_csr[EE];          // {src (bitcast int), edge_attr}

__device__ __forceinline__ float lrelu(float v) {
    return v > 0.0f ? v : 0.2f * v;
}

// packed dual-fp32 fma: d = a*b + c  (elementwise on {lo,hi})
__device__ __forceinline__ void fma2(u64& d, u64 a, u64 b, u64 c) {
    asm("fma.rn.f32x2 %0, %1, %2, %3;" : "=l"(d) : "l"(a), "l"(b), "l"(c));
}
__device__ __forceinline__ float fold2(u64 v) {
    float lo, hi;
    asm("mov.b64 {%0, %1}, %2;" : "=f"(lo), "=f"(hi) : "l"(v));
    return lo + hi;
}

__device__ __forceinline__ unsigned smem_u32(const void* p) {
    unsigned a;
    asm("{ .reg .u64 t; cvta.to.shared.u64 t, %1; cvt.u32.u64 %0, t; }"
        : "=r"(a) : "l"(p));
    return a;
}
__device__ __forceinline__ void cp16(unsigned dst, const void* src) {
    asm volatile("cp.async.cg.shared.global [%0], [%1], 16;"
                 :: "r"(dst), "l"(src) : "memory");
}
__device__ __forceinline__ void cp_commit() {
    asm volatile("cp.async.commit_group;" ::: "memory");
}
template <int N_>
__device__ __forceinline__ void cp_wait() {
    asm volatile("cp.async.wait_group %0;" :: "n"(N_) : "memory");
}

// --------------------------- CSR construction ------------------------------

__global__ void k_zero3(int n) {
    int i = blockIdx.x * blockDim.x + threadIdx.x;
    if (i < n) { g_cnt[i] = 0; g_fill[i] = 0; g_asum[i] = 0.0f; }
}

__global__ void k_deg(const int* __restrict__ dst, const float* __restrict__ ea, int e) {
    int i = blockIdx.x * blockDim.x + threadIdx.x;
    if (i >= e) return;
    int d = dst[i];
    atomicAdd(&g_cnt[d], 1);
    atomicAdd(&g_asum[d], ea[i]);
}

__global__ void k_mean(int n) {
    int i = blockIdx.x * blockDim.x + threadIdx.x;
    if (i >= n) return;
    g_mean[i] = g_asum[i] / (float)max(g_cnt[i], 1);
}

// Pass 1: per-block exclusive scan of cnt; block totals to g_bsum.
__global__ void k_scan1(int n) {
    __shared__ int s[256];
    int t = threadIdx.x;
    int i = blockIdx.x * 256 + t;
    int v = (i < n) ? g_cnt[i] : 0;
    s[t] = v;
    __syncthreads();
#pragma unroll
    for (int off = 1; off < 256; off <<= 1) {
        int add = (t >= off) ? s[t - off] : 0;
        __syncthreads();
        s[t] += add;
        __syncthreads();
    }
    if (i < n) g_rowptr[i] = s[t] - v;     // exclusive within block
    if (t == 255) g_bsum[blockIdx.x] = s[255];
}

// Pass 2: single-block exclusive scan of the m block totals (m <= 512).
__global__ void k_scan2(int m) {
    __shared__ int s[512];
    int t = threadIdx.x;
    int v = (t < m) ? g_bsum[t] : 0;
    s[t] = v;
    __syncthreads();
#pragma unroll
    for (int off = 1; off < 512; off <<= 1) {
        int add = (t >= off) ? s[t - off] : 0;
        __syncthreads();
        s[t] += add;
        __syncthreads();
    }
    if (t < m) g_bsum[t] = s[t] - v;       // exclusive block offsets, in place
}

// Pass 3: add block offsets; set rowptr[n] = e.
__global__ void k_scan3(int n, int e) {
    int i = blockIdx.x * 256 + threadIdx.x;
    if (i < n) g_rowptr[i] += g_bsum[blockIdx.x];
    if (i == 0) g_rowptr[n] = e;
}

__global__ void k_scatter(const int* __restrict__ src, const int* __restrict__ dst,
                          const float* __restrict__ ea, int e) {
    int i = blockIdx.x * blockDim.x + threadIdx.x;
    if (i >= e) return;
    int d = dst[i];
    int pos = g_rowptr[d] + atomicAdd(&g_fill[d], 1);
    g_csr[pos] = make_float2(__int_as_float(src[i]), ea[i]);
}

// ------------------------------- dense GEMM --------------------------------
// (unchanged from R13: persistent blocks, cp.async double buffer, warps
//  specialized per matrix, W columns register-resident)
template <int K>
__global__ void __launch_bounds__(256, 1)
k_gemm_lr(const float* __restrict__ x,
          const float* __restrict__ Wl, const float* __restrict__ bl,
          const float* __restrict__ Wr, const float* __restrict__ br,
          float* __restrict__ xl, float* __restrict__ xr, int n) {
    constexpr int KP = K + 4;
    constexpr int TILE_FLOATS = 32 * K;
    constexpr int CP_PER_THREAD = TILE_FLOATS / (256 * 4);
    extern __shared__ float sm[];
    float* sWl = sm;
    float* sWr = sm + F * KP;
    float* sx0 = sm + 2 * F * KP;
    float* sx1 = sx0 + TILE_FLOATS;

    const int ntiles = n >> 5;
    unsigned sx_u32[2] = { smem_u32(sx0), smem_u32(sx1) };

    int tile = blockIdx.x;
    if (tile < ntiles) {
        const char* srcb = (const char*)(x + (size_t)tile * TILE_FLOATS);
#pragma unroll
        for (int j = 0; j < CP_PER_THREAD; j++) {
            int off = (threadIdx.x + j * 256) * 16;
            cp16(sx_u32[0] + off, srcb + off);
        }
    }
    cp_commit();

    for (int i = threadIdx.x; i < K * F; i += 256) {
        int k = i / F, c = i % F;
        sWl[c * KP + k] = Wl[i];
        sWr[c * KP + k] = Wr[i];
    }
    __syncthreads();

    int lane = threadIdx.x & 31;
    int w    = threadIdx.x >> 5;
    const float* sWT = (w < 4) ? sWl : sWr;
    u64 wreg[K / 2];
#pragma unroll
    for (int i = 0; i < K / 2; i++)
        wreg[i] = *(const u64*)&sWT[lane * KP + 2 * i];

    float bias = (w < 4) ? bl[lane] : br[lane];
    float* outp = (w < 4) ? xl : xr;
    const int nodeoff = (w & 3) * 8;
    int buf = 0;

    for (; tile < ntiles; tile += gridDim.x) {
        int nxt = tile + gridDim.x;
        if (nxt < ntiles) {
            const char* srcb = (const char*)(x + (size_t)nxt * TILE_FLOATS);
#pragma unroll
            for (int j = 0; j < CP_PER_THREAD; j++) {
                int off = (threadIdx.x + j * 256) * 16;
                cp16(sx_u32[buf ^ 1] + off, srcb + off);
            }
        }
        cp_commit();
        cp_wait<1>();
        __syncthreads();

        const float* sx = buf ? sx1 : sx0;
        u64 acc[8] = {0ull, 0ull, 0ull, 0ull, 0ull, 0ull, 0ull, 0ull};
#pragma unroll
        for (int kk = 0; kk < K; kk += 4) {
#pragma unroll
            for (int j = 0; j < 8; j++) {
                ulonglong2 xv = *(const ulonglong2*)&sx[(nodeoff + j) * K + kk];
                fma2(acc[j], xv.x, wreg[kk / 2],     acc[j]);
                fma2(acc[j], xv.y, wreg[kk / 2 + 1], acc[j]);
            }
        }
        int base = tile * 32;
#pragma unroll
        for (int j = 0; j < 8; j++)
            outp[(base + nodeoff + j) * F + lane] = fold2(acc[j]) + bias;
        __syncthreads();
        buf ^= 1;
    }
}

// --------------------- fused per-node edge kernel --------------------------
// One warp per destination node. Lane = (j, s): j = lane>>3 selects one of 4
// parallel edge slots, s = lane&7 selects a 4-float chunk of the 32-dim
// feature. Per 4-edge chunk: gather xl[src] (float4/lane), score = att .
// lrelu(xl[src]+xr[v]+ea*We) reduced over s (3 shfl), p = exp(score),
// accumulate p and p*xl in registers. Self-loop (attr=mean) handled inline
// by the j==0 group. Final j-group reduction (shfl 8,16), normalize by z,
// add bias, optional relu, write out[v] once. No atomics, no init, no epi.
template <bool RELU>
__global__ void k_node(const float* __restrict__ We, const float* __restrict__ att,
                       const float* __restrict__ bias, float* __restrict__ out, int n) {
    int gw = (blockIdx.x * blockDim.x + threadIdx.x) >> 5;
    if (gw >= n) return;                 // uniform per warp
    int lane = threadIdx.x & 31;
    int j = lane >> 3, s = lane & 7;

    const float4* xl4 = (const float4*)g_xl;
    float4 vx = ((const float4*)g_xr)[gw * 8 + s];
    float4 w4 = __ldg((const float4*)We + s);
    float4 t4 = __ldg((const float4*)att + s);

    float ax = 0.0f, ay = 0.0f, az = 0.0f, aw = 0.0f, z = 0.0f;

    // self-loop (contributes via j==0 group only)
    {
        float4 u = xl4[gw * 8 + s];
        float a = g_mean[gw];
        float sc;
        sc = lrelu(u.x + vx.x + a * w4.x) * t4.x;
        sc = fmaf(lrelu(u.y + vx.y + a * w4.y), t4.y, sc);
        sc = fmaf(lrelu(u.z + vx.z + a * w4.z), t4.z, sc);
        sc = fmaf(lrelu(u.w + vx.w + a * w4.w), t4.w, sc);
        sc += __shfl_xor_sync(0xffffffffu, sc, 4);
        sc += __shfl_xor_sync(0xffffffffu, sc, 2);
        sc += __shfl_xor_sync(0xffffffffu, sc, 1);
        if (j == 0) {
            float p = __expf(sc);
            ax = p * u.x; ay = p * u.y; az = p * u.z; aw = p * u.w;
            z = p;
        }
    }

    int start = g_rowptr[gw], end = g_rowptr[gw + 1];
    for (int base = start; base < end; base += 4) {
        int eidx = base + j;
        bool valid = eidx < end;
        float2 rec = g_csr[valid ? eidx : base];
        int si = __float_as_int(rec.x);
        float a = rec.y;
        float4 u = xl4[si * 8 + s];
        float sc;
        sc = lrelu(u.x + vx.x + a * w4.x) * t4.x;
        sc = fmaf(lrelu(u.y + vx.y + a * w4.y), t4.y, sc);
        sc = fmaf(lrelu(u.z + vx.z + a * w4.z), t4.z, sc);
        sc = fmaf(lrelu(u.w + vx.w + a * w4.w), t4.w, sc);
        sc += __shfl_xor_sync(0xffffffffu, sc, 4);
        sc += __shfl_xor_sync(0xffffffffu, sc, 2);
        sc += __shfl_xor_sync(0xffffffffu, sc, 1);
        float p = valid ? __expf(sc) : 0.0f;
        ax = fmaf(p, u.x, ax); ay = fmaf(p, u.y, ay);
        az = fmaf(p, u.z, az); aw = fmaf(p, u.w, aw);
        z += p;
    }

    // reduce the 4 j-groups
#pragma unroll
    for (int m = 8; m <= 16; m <<= 1) {
        ax += __shfl_xor_sync(0xffffffffu, ax, m);
        ay += __shfl_xor_sync(0xffffffffu, ay, m);
        az += __shfl_xor_sync(0xffffffffu, az, m);
        aw += __shfl_xor_sync(0xffffffffu, aw, m);
        z  += __shfl_xor_sync(0xffffffffu, z,  m);
    }

    if (j == 0) {
        float inv = 1.0f / z;
        float4 b4 = __ldg((const float4*)bias + s);
        float4 o;
        o.x = fmaf(ax, inv, b4.x);
        o.y = fmaf(ay, inv, b4.y);
        o.z = fmaf(az, inv, b4.z);
        o.w = fmaf(aw, inv, b4.w);
        if (RELU) {
            o.x = fmaxf(o.x, 0.0f); o.y = fmaxf(o.y, 0.0f);
            o.z = fmaxf(o.z, 0.0f); o.w = fmaxf(o.w, 0.0f);
        }
        ((float4*)out)[gw * 8 + s] = o;
    }
}

// ---------------------------------------------------------------------------

extern "C" void kernel_launch(void* const* d_in, const int* in_sizes, int n_in,
                              void* d_out, int out_size) {
    const float* x   = (const float*)d_in[0];
    const int*   src = (const int*)d_in[1];
    const int*   dst = (const int*)d_in[2];
    const float* ea  = (const float*)d_in[3];
    const float* Wl1 = (const float*)d_in[4];
    const float* bl1 = (const float*)d_in[5];
    const float* Wr1 = (const float*)d_in[6];
    const float* br1 = (const float*)d_in[7];
    const float* We1 = (const float*)d_in[8];
    const float* at1 = (const float*)d_in[9];
    const float* b1  = (const float*)d_in[10];
    const float* Wl2 = (const float*)d_in[11];
    const float* bl2 = (const float*)d_in[12];
    const float* Wr2 = (const float*)d_in[13];
    const float* br2 = (const float*)d_in[14];
    const float* We2 = (const float*)d_in[15];
    const float* at2 = (const float*)d_in[16];
    const float* b2  = (const float*)d_in[17];

    const int n    = in_sizes[0] / 128;   // 100000
    const int e    = in_sizes[1];         // 1600000

    float* out = (float*)d_out;
    float* d_xl; cudaGetSymbolAddress((void**)&d_xl, g_xl);
    float* d_xr; cudaGetSymbolAddress((void**)&d_xr, g_xr);
    float* d_h;  cudaGetSymbolAddress((void**)&d_h,  g_h);

    const int T = 256;
    const int gN  = (n + T - 1) / T;
    const int gE  = (e + T - 1) / T;
    const int nsb = (n + 255) / 256;           // scan blocks (391)
    const int gW  = (n * 32 + T - 1) / T;      // warp-per-node grid
    const int gP  = 148;                       // persistent GEMM grid

    const int smem128 = (2 * F * (128 + 4) + 2 * 32 * 128) * sizeof(float); // ~66.5KB
    const int smem32  = (2 * F * (32 + 4)  + 2 * 32 * 32)  * sizeof(float);
    cudaFuncSetAttribute(k_gemm_lr<128>, cudaFuncAttributeMaxDynamicSharedMemorySize, smem128);

    // ---- CSR build (once; reused by both layers) ----
    k_zero3<<<gN, T>>>(n);
    k_deg<<<gE, T>>>(dst, ea, e);
    k_scan1<<<nsb, 256>>>(n);
    k_scan2<<<1, 512>>>(nsb);
    k_scan3<<<nsb, 256>>>(n, e);
    k_mean<<<gN, T>>>(n);
    k_scatter<<<gE, T>>>(src, dst, ea, e);

    // ---------------- Layer 1 ----------------
    k_gemm_lr<128><<<gP, T, smem128>>>(x, Wl1, bl1, Wr1, br1, d_xl, d_xr, n);
    k_node<true><<<gW, T>>>(We1, at1, b1, d_h, n);

    // ---------------- Layer 2 ----------------
    k_gemm_lr<32><<<gP, T, smem32>>>(d_h, Wl2, bl2, Wr2, br2, d_xl, d_xr, n);
    k_node<false><<<gW, T>>>(We2, at2, b2, out, n);
}